// round 7
// baseline (speedup 1.0000x reference)
#include <cuda_runtime.h>
#include <cuda_bf16.h>
#include <cstdint>

#define HIDDEN   160
#define IN_DIM   784
#define NLAYERS  32
#define NCLASSES 10
#define BM       128
#define NTH      256
#define NTILES   20            // HIDDEN / 8
#define LDA      168           // padded row length in bf16 elems
#define STRB     (LDA * 2)     // 336 bytes per row

// SMEM byte offsets (all 16B aligned)
#define A_HI 0
#define A_LO (A_HI + BM * STRB)        // 43008
#define W_HI (A_LO + BM * STRB)        // 86016
#define W_LO (W_HI + HIDDEN * STRB)    // 139776
#define SM_TOTAL (W_LO + HIDDEN * STRB) // 193536

__device__ __forceinline__ uint32_t smem_u32(const void* p) {
    uint32_t a;
    asm("{ .reg .u64 t; cvta.to.shared.u64 t, %1; cvt.u32.u64 %0, t; }"
        : "=r"(a) : "l"(p));
    return a;
}

__device__ __forceinline__ void ldsm_x4(uint32_t (&r)[4], uint32_t addr) {
    asm volatile("ldmatrix.sync.aligned.m8n8.x4.shared.b16 {%0,%1,%2,%3}, [%4];"
        : "=r"(r[0]), "=r"(r[1]), "=r"(r[2]), "=r"(r[3]) : "r"(addr));
}

__device__ __forceinline__ void ldsm_x2t(uint32_t (&r)[2], uint32_t addr) {
    asm volatile("ldmatrix.sync.aligned.m8n8.x2.trans.shared.b16 {%0,%1}, [%2];"
        : "=r"(r[0]), "=r"(r[1]) : "r"(addr));
}

__device__ __forceinline__ void mma_bf16(float (&d)[4], const uint32_t (&a)[4],
                                         const uint32_t (&b)[2]) {
    asm volatile(
        "mma.sync.aligned.m16n8k16.row.col.f32.bf16.bf16.f32 "
        "{%0,%1,%2,%3}, {%4,%5,%6,%7}, {%8,%9}, {%0,%1,%2,%3};"
        : "+f"(d[0]), "+f"(d[1]), "+f"(d[2]), "+f"(d[3])
        : "r"(a[0]), "r"(a[1]), "r"(a[2]), "r"(a[3]), "r"(b[0]), "r"(b[1]));
}

// Split v0,v1 into bf16 hi+lo pairs and store (2x STS.32).
__device__ __forceinline__ void split_store(char* smem, int off_hi, int off_lo,
                                            float v0, float v1) {
    __nv_bfloat16 h0 = __float2bfloat16(v0);
    __nv_bfloat16 h1 = __float2bfloat16(v1);
    float l0 = v0 - __bfloat162float(h0);
    float l1 = v1 - __bfloat162float(h1);
    __nv_bfloat162 hp = __halves2bfloat162(h0, h1);
    __nv_bfloat162 lp = __halves2bfloat162(__float2bfloat16(l0), __float2bfloat16(l1));
    *reinterpret_cast<uint32_t*>(smem + off_hi) = *reinterpret_cast<uint32_t*>(&hp);
    *reinterpret_cast<uint32_t*>(smem + off_lo) = *reinterpret_cast<uint32_t*>(&lp);
}

// One K=160 pass of split-bf16 MMA: acc += A(128x160) @ W(160x160), warp-tiled.
__device__ __forceinline__ void do_mma10(float (&acc)[NTILES][4], uint32_t sb,
                                         int a_lane_off, int b_lane_off) {
    for (int ks = 0; ks < 10; ks++) {
        uint32_t ah[4], al[4];
        ldsm_x4(ah, sb + A_HI + a_lane_off + ks * 32);
        ldsm_x4(al, sb + A_LO + a_lane_off + ks * 32);
        uint32_t wrow = sb + b_lane_off + ks * 16 * STRB;
#pragma unroll
        for (int t = 0; t < NTILES; t++) {
            uint32_t bh[2], bl[2];
            ldsm_x2t(bh, wrow + W_HI + t * 16);
            ldsm_x2t(bl, wrow + W_LO + t * 16);
            mma_bf16(acc[t], ah, bh);
            mma_bf16(acc[t], ah, bl);
            mma_bf16(acc[t], al, bh);
        }
    }
}

__global__ void __launch_bounds__(NTH, 1)
resmlp_kernel(const float* __restrict__ x,  const float* __restrict__ ew,
              const float* __restrict__ eb, const float* __restrict__ lw,
              const float* __restrict__ hw, const float* __restrict__ hbias,
              float* __restrict__ out) {
    extern __shared__ char smem[];
    const uint32_t sb = smem_u32(smem);
    const int tid  = threadIdx.x;
    const int lane = tid & 31;
    const int w    = tid >> 5;
    const int cta  = blockIdx.x;

    // ldmatrix per-lane address offsets (bytes)
    const int a_lane_off = (16 * w + (lane & 15)) * STRB + (lane >> 4) * 16;
    const int b_lane_off = (lane & 15) * STRB;

    // accumulator fragment -> (row, col) mapping
    const int qr = lane >> 2;          // 0..7
    const int qc = (lane & 3) * 2;     // 0,2,4,6

    float acc[NTILES][4];
#pragma unroll
    for (int t = 0; t < NTILES; t++)
#pragma unroll
        for (int i = 0; i < 4; i++) acc[t][i] = 0.0f;

    // ---------------- Embed: h = x @ ew + eb, K=784 as 5 chunks of 160 ----------------
    const float* xbase = x + (size_t)cta * BM * IN_DIM;
    for (int c = 0; c < 5; c++) {
        __syncthreads();  // previous chunk's mma done before restaging A/W
        // stage x chunk -> A (hi/lo): 128 rows x 80 pairs
        for (int idx = tid; idx < BM * 80; idx += NTH) {
            int r = idx / 80, p = idx - r * 80;
            int k = c * 160 + 2 * p;
            float2 v;
            if (k < IN_DIM) v = *reinterpret_cast<const float2*>(xbase + (size_t)r * IN_DIM + k);
            else            v = make_float2(0.0f, 0.0f);
            int off = r * STRB + p * 4;
            split_store(smem, A_HI + off, A_LO + off, v.x, v.y);
        }
        // stage ew chunk -> W (hi/lo): 160 k-rows x 80 n-pairs
        for (int idx = tid; idx < HIDDEN * 80; idx += NTH) {
            int kl = idx / 80, np = idx - kl * 80;
            int kg = c * 160 + kl;
            float2 v;
            if (kg < IN_DIM) v = *reinterpret_cast<const float2*>(ew + (size_t)kg * HIDDEN + 2 * np);
            else             v = make_float2(0.0f, 0.0f);
            int off = kl * STRB + np * 4;
            split_store(smem, W_HI + off, W_LO + off, v.x, v.y);
        }
        __syncthreads();
        do_mma10(acc, sb, a_lane_off, b_lane_off);
    }
    // embed epilogue: h = acc + eb  -> write split h into A tiles
    {
        const int r0 = 16 * w + qr;
#pragma unroll
        for (int t = 0; t < NTILES; t++) {
            const int cc = 8 * t + qc;
            float b0 = eb[cc], b1 = eb[cc + 1];
#pragma unroll
            for (int hlf = 0; hlf < 2; hlf++) {
                int off = (r0 + 8 * hlf) * STRB + cc * 2;
                split_store(smem, A_HI + off, A_LO + off,
                            acc[t][2 * hlf] + b0, acc[t][2 * hlf + 1] + b1);
            }
        }
    }

    // ---------------- 32 residual layers: h = relu(h @ W) + h ----------------
    for (int l = 0; l < NLAYERS; l++) {
        __syncthreads();  // all warps done with previous W reads + epilogue
        const float* W = lw + (size_t)l * HIDDEN * HIDDEN;
        for (int idx = tid; idx < HIDDEN * 80; idx += NTH) {
            int k = idx / 80, np = idx - k * 80;
            float2 v = *reinterpret_cast<const float2*>(W + (size_t)k * HIDDEN + 2 * np);
            int off = k * STRB + np * 4;
            split_store(smem, W_HI + off, W_LO + off, v.x, v.y);
        }
        __syncthreads();
#pragma unroll
        for (int t = 0; t < NTILES; t++)
#pragma unroll
            for (int i = 0; i < 4; i++) acc[t][i] = 0.0f;
        do_mma10(acc, sb, a_lane_off, b_lane_off);
        // epilogue: read old h (hi+lo), relu + residual, re-split in place
        const int r0 = 16 * w + qr;
#pragma unroll
        for (int t = 0; t < NTILES; t++) {
            const int cb = (8 * t + qc) * 2;
#pragma unroll
            for (int hlf = 0; hlf < 2; hlf++) {
                int off = (r0 + 8 * hlf) * STRB + cb;
                uint32_t hp = *reinterpret_cast<uint32_t*>(smem + A_HI + off);
                uint32_t lp = *reinterpret_cast<uint32_t*>(smem + A_LO + off);
                __nv_bfloat162 hb2 = *reinterpret_cast<__nv_bfloat162*>(&hp);
                __nv_bfloat162 lb2 = *reinterpret_cast<__nv_bfloat162*>(&lp);
                float o0 = __low2float(hb2)  + __low2float(lb2);
                float o1 = __high2float(hb2) + __high2float(lb2);
                float n0 = fmaxf(acc[t][2 * hlf + 0], 0.0f) + o0;
                float n1 = fmaxf(acc[t][2 * hlf + 1], 0.0f) + o1;
                split_store(smem, A_HI + off, A_LO + off, n0, n1);
            }
        }
    }

    // ---------------- Head: out = h @ head_w + head_b (SIMT) ----------------
    __syncthreads();
    float* hwS = reinterpret_cast<float*>(smem + W_HI);  // reuse W region
    for (int idx = tid; idx < HIDDEN * NCLASSES; idx += NTH) hwS[idx] = hw[idx];
    __syncthreads();
    if (tid < BM) {
        float a[NCLASSES];
#pragma unroll
        for (int cc = 0; cc < NCLASSES; cc++) a[cc] = hbias[cc];
        for (int k = 0; k < HIDDEN; k++) {
            int off = tid * STRB + k * 2;
            float hv = __bfloat162float(*reinterpret_cast<__nv_bfloat16*>(smem + A_HI + off))
                     + __bfloat162float(*reinterpret_cast<__nv_bfloat16*>(smem + A_LO + off));
#pragma unroll
            for (int cc = 0; cc < NCLASSES; cc++)
                a[cc] = fmaf(hv, hwS[k * NCLASSES + cc], a[cc]);
        }
        const size_t grow = (size_t)cta * BM + tid;
#pragma unroll
        for (int cc = 0; cc < NCLASSES; cc++) out[grow * NCLASSES + cc] = a[cc];
    }
}

extern "C" void kernel_launch(void* const* d_in, const int* in_sizes, int n_in,
                              void* d_out, int out_size) {
    const float* x  = (const float*)d_in[0];
    const float* ew = (const float*)d_in[1];
    const float* eb = (const float*)d_in[2];
    const float* lw = (const float*)d_in[3];
    const float* hw = (const float*)d_in[4];
    const float* hb = (const float*)d_in[5];
    float* out = (float*)d_out;

    const int B = in_sizes[0] / IN_DIM;   // 65536
    const int blocks = B / BM;            // 512

    cudaFuncSetAttribute(resmlp_kernel,
                         cudaFuncAttributeMaxDynamicSharedMemorySize, SM_TOTAL);
    resmlp_kernel<<<blocks, NTH, SM_TOTAL>>>(x, ew, eb, lw, hw, hb, out);
}

// round 9
// speedup vs baseline: 1.4975x; 1.4975x over previous
#include <cuda_runtime.h>
#include <cuda_bf16.h>
#include <cstdint>

#define HIDDEN   160
#define IN_DIM   784
#define NLAYERS  32
#define NCLASSES 10
#define BM       128
#define NTH      256
#define LDA      168             // padded row length (bf16 elems), 336B stride
#define STRB     (LDA * 2)

// ---- layer-phase SMEM: two W buffers, each [hi|lo] plane of 160x168 bf16 ----
#define WPLANE   53760           // 160*168*2 bytes
#define WBUF     107520          // hi+lo
#define SM_TOTAL (2 * WBUF)      // 215040 B

// ---- embed-phase SMEM layout (union with W buffers) ----
#define EA_HI 0
#define EA_LO (EA_HI + BM * STRB)      // 43008
#define EW_HI (EA_LO + BM * STRB)      // 86016
#define EW_LO (EW_HI + WPLANE)         // 139776  (end 193536 < SM_TOTAL)

// ---- pre-split weights in device-global scratch ----
// layer l: contiguous 107520B = [hi 160x168][lo 160x168] bf16
__device__ __align__(16) __nv_bfloat16 g_lw[NLAYERS * 2 * HIDDEN * LDA];
// embed: [hi 800x168][lo 800x168] (rows >=784 zero, cols >=160 zero)
__device__ __align__(16) __nv_bfloat16 g_ew[2 * 800 * LDA];

__device__ __forceinline__ uint32_t smem_u32(const void* p) {
    uint32_t a;
    asm("{ .reg .u64 t; cvta.to.shared.u64 t, %1; cvt.u32.u64 %0, t; }"
        : "=r"(a) : "l"(p));
    return a;
}

__device__ __forceinline__ void ldsm_x4(uint32_t (&r)[4], uint32_t addr) {
    asm volatile("ldmatrix.sync.aligned.m8n8.x4.shared.b16 {%0,%1,%2,%3}, [%4];"
        : "=r"(r[0]), "=r"(r[1]), "=r"(r[2]), "=r"(r[3]) : "r"(addr));
}

__device__ __forceinline__ void ldsm_x4t(uint32_t (&r)[4], uint32_t addr) {
    asm volatile("ldmatrix.sync.aligned.m8n8.x4.trans.shared.b16 {%0,%1,%2,%3}, [%4];"
        : "=r"(r[0]), "=r"(r[1]), "=r"(r[2]), "=r"(r[3]) : "r"(addr));
}

__device__ __forceinline__ void mma_bf16(float (&d)[4], const uint32_t* a,
                                         uint32_t b0, uint32_t b1) {
    asm volatile(
        "mma.sync.aligned.m16n8k16.row.col.f32.bf16.bf16.f32 "
        "{%0,%1,%2,%3}, {%4,%5,%6,%7}, {%8,%9}, {%0,%1,%2,%3};"
        : "+f"(d[0]), "+f"(d[1]), "+f"(d[2]), "+f"(d[3])
        : "r"(a[0]), "r"(a[1]), "r"(a[2]), "r"(a[3]), "r"(b0), "r"(b1));
}

__device__ __forceinline__ void cp16(uint32_t dst, const void* src) {
    asm volatile("cp.async.cg.shared.global [%0], [%1], 16;"
                 :: "r"(dst), "l"(src) : "memory");
}
#define CP_COMMIT() asm volatile("cp.async.commit_group;" ::: "memory")
#define CP_WAIT(n)  asm volatile("cp.async.wait_group %0;" :: "n"(n) : "memory")

// split (v0,v1) into packed bf16x2 hi/lo register pair
__device__ __forceinline__ void split_pack(float v0, float v1, uint32_t& hi, uint32_t& lo) {
    __nv_bfloat16 h0 = __float2bfloat16(v0);
    __nv_bfloat16 h1 = __float2bfloat16(v1);
    float l0 = v0 - __bfloat162float(h0);
    float l1 = v1 - __bfloat162float(h1);
    __nv_bfloat162 hp = __halves2bfloat162(h0, h1);
    __nv_bfloat162 lp = __halves2bfloat162(__float2bfloat16(l0), __float2bfloat16(l1));
    hi = *reinterpret_cast<uint32_t*>(&hp);
    lo = *reinterpret_cast<uint32_t*>(&lp);
}

__device__ __forceinline__ void split_store(char* smem, int off_hi, int off_lo,
                                            float v0, float v1) {
    uint32_t hi, lo;
    split_pack(v0, v1, hi, lo);
    *reinterpret_cast<uint32_t*>(smem + off_hi) = hi;
    *reinterpret_cast<uint32_t*>(smem + off_lo) = lo;
}

__device__ __forceinline__ float2 unsplit(uint32_t hi, uint32_t lo) {
    __nv_bfloat162 h = *reinterpret_cast<__nv_bfloat162*>(&hi);
    __nv_bfloat162 l = *reinterpret_cast<__nv_bfloat162*>(&lo);
    return make_float2(__low2float(h) + __low2float(l),
                       __high2float(h) + __high2float(l));
}

// ---------------- prep kernel: split weights into g_lw / g_ew ----------------
__global__ void prep_kernel(const float* __restrict__ lw, const float* __restrict__ ew) {
    const int TOT_L = NLAYERS * HIDDEN * LDA;   // 860160
    const int TOT_E = 800 * LDA;                // 134400
    for (int i = blockIdx.x * blockDim.x + threadIdx.x; i < TOT_L + TOT_E;
         i += gridDim.x * blockDim.x) {
        if (i < TOT_L) {
            int l = i / (HIDDEN * LDA);
            int rc = i - l * (HIDDEN * LDA);
            int r = rc / LDA;              // k row
            int c = rc - r * LDA;          // n col
            float v = (c < HIDDEN) ? lw[(size_t)l * HIDDEN * HIDDEN + r * HIDDEN + c] : 0.0f;
            __nv_bfloat16 hb = __float2bfloat16(v);
            __nv_bfloat16 lb = __float2bfloat16(v - __bfloat162float(hb));
            size_t base = (size_t)l * (2 * HIDDEN * LDA) + (size_t)r * LDA + c;
            g_lw[base] = hb;
            g_lw[base + HIDDEN * LDA] = lb;
        } else {
            int j = i - TOT_L;
            int r = j / LDA;               // k row 0..799
            int c = j - r * LDA;
            float v = (r < IN_DIM && c < HIDDEN) ? ew[(size_t)r * HIDDEN + c] : 0.0f;
            __nv_bfloat16 hb = __float2bfloat16(v);
            __nv_bfloat16 lb = __float2bfloat16(v - __bfloat162float(hb));
            g_ew[(size_t)r * LDA + c] = hb;
            g_ew[(size_t)800 * LDA + (size_t)r * LDA + c] = lb;
        }
    }
}

// ---------------- main kernel ----------------
__global__ void __launch_bounds__(NTH, 1)
resmlp_kernel(const float* __restrict__ x,  const float* __restrict__ eb,
              const float* __restrict__ hw, const float* __restrict__ hbias,
              float* __restrict__ out) {
    extern __shared__ char smem[];
    const uint32_t sb = smem_u32(smem);
    const int tid  = threadIdx.x;
    const int lane = tid & 31;
    const int w    = tid >> 5;
    const int cta  = blockIdx.x;

    const int a_lane_off = (16 * w + (lane & 15)) * STRB + (lane >> 4) * 16;
    const int b4_off     = (lane & 15) * STRB + (lane >> 4) * 16;
    const int qr = lane >> 2;
    const int qc = (lane & 3) * 2;

    float acc[20][4];
#pragma unroll
    for (int t = 0; t < 20; t++)
#pragma unroll
        for (int i = 0; i < 4; i++) acc[t][i] = 0.0f;

    // ================= Embed: h = x @ ew + eb, K padded to 800 (5x160) =================
    const float* xbase = x + (size_t)cta * BM * IN_DIM;
    const char* gew = reinterpret_cast<const char*>(g_ew);
    for (int c = 0; c < 5; c++) {
        if (c) __syncthreads();            // prior chunk's mma done before restage
        // W chunk via cp.async (pre-split, pre-padded)
        for (int j = tid * 16; j < WPLANE; j += NTH * 16) {
            cp16(sb + EW_HI + j, gew + (size_t)c * WPLANE + j);
            cp16(sb + EW_LO + j, gew + (size_t)800 * LDA * 2 + (size_t)c * WPLANE + j);
        }
        CP_COMMIT();
        // x chunk staged + split manually
        for (int idx = tid; idx < BM * 80; idx += NTH) {
            int r = idx / 80, p = idx - r * 80;
            int k = c * 160 + 2 * p;
            float2 v;
            if (k < IN_DIM) v = *reinterpret_cast<const float2*>(xbase + (size_t)r * IN_DIM + k);
            else            v = make_float2(0.0f, 0.0f);
            int off = r * STRB + p * 4;
            split_store(smem, EA_HI + off, EA_LO + off, v.x, v.y);
        }
        CP_WAIT(0);
        __syncthreads();
#pragma unroll
        for (int ks = 0; ks < 10; ks++) {
            uint32_t ah4[4], al4[4];
            ldsm_x4(ah4, sb + EA_HI + a_lane_off + ks * 32);
            ldsm_x4(al4, sb + EA_LO + a_lane_off + ks * 32);
            uint32_t wrow = sb + b4_off + ks * (16 * STRB);
#pragma unroll
            for (int tt = 0; tt < 10; tt++) {
                uint32_t bh[4], bl[4];
                ldsm_x4t(bh, wrow + EW_HI + tt * 32);
                ldsm_x4t(bl, wrow + EW_LO + tt * 32);
                mma_bf16(acc[2 * tt],     ah4, bh[0], bh[1]);
                mma_bf16(acc[2 * tt],     ah4, bl[0], bl[1]);
                mma_bf16(acc[2 * tt],     al4, bh[0], bh[1]);
                mma_bf16(acc[2 * tt + 1], ah4, bh[2], bh[3]);
                mma_bf16(acc[2 * tt + 1], ah4, bl[2], bl[3]);
                mma_bf16(acc[2 * tt + 1], al4, bh[2], bh[3]);
            }
        }
    }
    // bias
#pragma unroll
    for (int t = 0; t < 20; t++) {
        float b0 = eb[8 * t + qc], b1 = eb[8 * t + qc + 1];
        acc[t][0] += b0; acc[t][1] += b1;
        acc[t][2] += b0; acc[t][3] += b1;
    }
    __syncthreads();   // embed smem region free

    // ================= 32 residual layers, h register-resident =================
    const char* glw = reinterpret_cast<const char*>(g_lw);
    // prologue: prefetch layer 0 into buf 0
    for (int j = tid * 16; j < WBUF; j += NTH * 16)
        cp16(sb + j, glw + j);
    CP_COMMIT();

    float* af = &acc[0][0];
    for (int l = 0; l < NLAYERS; l++) {
        const uint32_t wb = (l & 1) ? WBUF : 0;
        if (l + 1 < NLAYERS) {
            const uint32_t nb = ((l + 1) & 1) ? WBUF : 0;
            const char* src = glw + (size_t)(l + 1) * WBUF;
            for (int j = tid * 16; j < WBUF; j += NTH * 16)
                cp16(sb + nb + j, src + j);
            CP_COMMIT();
            CP_WAIT(1);
        } else {
            CP_WAIT(0);
        }
        __syncthreads();

        // snapshot h -> (ah, al), zero acc.  D-fragment == next A-fragment layout.
        uint32_t ah[40], al[40];
#pragma unroll
        for (int j = 0; j < 40; j++) {
            split_pack(af[2 * j], af[2 * j + 1], ah[j], al[j]);
            af[2 * j] = 0.0f; af[2 * j + 1] = 0.0f;
        }

#pragma unroll
        for (int ks = 0; ks < 10; ks++) {
            const uint32_t* Ah = &ah[ks * 4];
            const uint32_t* Al = &al[ks * 4];
            uint32_t wrow = sb + wb + b4_off + ks * (16 * STRB);
#pragma unroll
            for (int tt = 0; tt < 10; tt++) {
                uint32_t bh[4], bl[4];
                ldsm_x4t(bh, wrow + tt * 32);
                ldsm_x4t(bl, wrow + WPLANE + tt * 32);
                mma_bf16(acc[2 * tt],     Ah, bh[0], bh[1]);
                mma_bf16(acc[2 * tt],     Ah, bl[0], bl[1]);
                mma_bf16(acc[2 * tt],     Al, bh[0], bh[1]);
                mma_bf16(acc[2 * tt + 1], Ah, bh[2], bh[3]);
                mma_bf16(acc[2 * tt + 1], Ah, bl[2], bl[3]);
                mma_bf16(acc[2 * tt + 1], Al, bh[2], bh[3]);
            }
        }

        // epilogue in registers: h = relu(gemm) + h_old
#pragma unroll
        for (int j = 0; j < 40; j++) {
            float2 ho = unsplit(ah[j], al[j]);
            af[2 * j]     = fmaxf(af[2 * j],     0.0f) + ho.x;
            af[2 * j + 1] = fmaxf(af[2 * j + 1], 0.0f) + ho.y;
        }
        __syncthreads();   // everyone done reading buf wb before it is overwritten
    }

    // ================= Head: out = h @ head_w + head_b =================
    float* hsm = reinterpret_cast<float*>(smem);            // 128x160 f32 = 81920B
    float* hwS = reinterpret_cast<float*>(smem + 86016);    // 1600 f32
    {
        const int r0 = 16 * w + qr;
#pragma unroll
        for (int t = 0; t < 20; t++) {
            const int cc = 8 * t + qc;
            hsm[r0 * HIDDEN + cc]           = acc[t][0];
            hsm[r0 * HIDDEN + cc + 1]       = acc[t][1];
            hsm[(r0 + 8) * HIDDEN + cc]     = acc[t][2];
            hsm[(r0 + 8) * HIDDEN + cc + 1] = acc[t][3];
        }
    }
    for (int idx = tid; idx < HIDDEN * NCLASSES; idx += NTH) hwS[idx] = hw[idx];
    __syncthreads();
    if (tid < BM) {
        float a[NCLASSES];
#pragma unroll
        for (int cc = 0; cc < NCLASSES; cc++) a[cc] = hbias[cc];
        for (int k = 0; k < HIDDEN; k++) {
            float hv = hsm[tid * HIDDEN + k];
#pragma unroll
            for (int cc = 0; cc < NCLASSES; cc++)
                a[cc] = fmaf(hv, hwS[k * NCLASSES + cc], a[cc]);
        }
        const size_t grow = (size_t)cta * BM + tid;
#pragma unroll
        for (int cc = 0; cc < NCLASSES; cc++) out[grow * NCLASSES + cc] = a[cc];
    }
}

extern "C" void kernel_launch(void* const* d_in, const int* in_sizes, int n_in,
                              void* d_out, int out_size) {
    const float* x  = (const float*)d_in[0];
    const float* ew = (const float*)d_in[1];
    const float* eb = (const float*)d_in[2];
    const float* lw = (const float*)d_in[3];
    const float* hw = (const float*)d_in[4];
    const float* hb = (const float*)d_in[5];
    float* out = (float*)d_out;

    const int B = in_sizes[0] / IN_DIM;   // 65536
    const int blocks = B / BM;            // 512

    prep_kernel<<<512, 256>>>(lw, ew);

    cudaFuncSetAttribute(resmlp_kernel,
                         cudaFuncAttributeMaxDynamicSharedMemorySize, SM_TOTAL);
    resmlp_kernel<<<blocks, NTH, SM_TOTAL>>>(x, eb, hw, hb, out);
}